// round 15
// baseline (speedup 1.0000x reference)
#include <cuda_runtime.h>
#include <cuda_fp16.h>
#include <stdint.h>
#include <stdlib.h>

// ---------------------------------------------------------------------------
// GCN 2-layer forward, N=100k, E=1.6M, d=64.
// Key identity: aggregate/transform commute => stage z=(x*rout)@W1 (fp16),
// then layer 1 collapses to a pure gather: q = rout*(relu(rin*Sum z + b1).w2r).
// Feature pairs are permuted as (lane, lane+32) everywhere (transparent to the
// final dot products); WPAD=68 keeps LDS.128 16B-aligned + conflict-free.
// Pipeline (6 launches; pure gather at index 3 = the ncu-captured slot):
//  0 k_deg        degrees via atomics (cnt arrays zero by module init / reset)
//  1 k_scan_stage scan tiles: decoupled-lookback scan of cnt_in -> row_ptr/
//                 cursor;  gemm blocks: z = (x*rout)@W1 -> fp16
//  2 k_fill       CSR fill (src only)
//  3 k_agg_q      warp per row: agg = z_self + sum z[src] (lane-owned pairs),
//                 q = rout*(relu(rin*agg+b1) . w2r)   [no smem tiles, no sync]
//  4 k_out        out = rin*(q_self + sum_in q) + (b2.Wr + br)
//  5 k_reset      re-zero cnt/desc/ticket for the next replay
// ---------------------------------------------------------------------------

#define MAXN 100352
#define MAXE 1605632
#define D 64
#define WPAD 68                      // 272B row stride: 16B-aligned, no conflicts
#define FULL 0xffffffffu
#define SCAN_TILE 1024
#define MAX_TILES ((MAXN + SCAN_TILE - 1) / SCAN_TILE)

__device__ int   g_cnt_out[MAXN];
__device__ int   g_cnt_in[MAXN];
__device__ int   g_row_ptr[MAXN + 1];
__device__ int   g_cursor[MAXN];
__device__ int   g_csr[MAXE];              // src only (4 B/edge)
__device__ __half2 g_z[MAXN * D / 2];      // staged z, fp16, pair (lane,lane+32)
__device__ float g_q[MAXN];
__device__ unsigned long long g_desc[MAX_TILES];  // lookback: status<<32 | value
__device__ unsigned g_scan_ticket;

__attribute__((constructor))
static void _eager_modules() { setenv("CUDA_MODULE_LOADING", "EAGER", 1); }

__device__ __forceinline__ int clampi(int v, int n) { return min(max(v, 0), n - 1); }

// ------------------------------- degrees -----------------------------------

__global__ void k_deg(const int* __restrict__ src, const int* __restrict__ dst,
                      int e, int n) {
    int t = blockIdx.x * blockDim.x + threadIdx.x;
    if (t >= e) return;
    atomicAdd(&g_cnt_out[clampi(src[t], n)], 1);
    atomicAdd(&g_cnt_in[clampi(dst[t], n)], 1);
}

// ------- single-pass scan (decoupled lookback) + staging GEMM blocks --------

__global__ __launch_bounds__(256)
void k_scan_stage(const float* __restrict__ x, const float* __restrict__ W1,
                  int n, int ntiles) {
    __shared__ float WsT[D][WPAD];       // 17 KB (gemm blocks)
    __shared__ float Us[64][D];          // 16 KB (gemm blocks)
    __shared__ int   sh_tile, sh_prefix;
    __shared__ int   warp_agg[8];

    const int t = threadIdx.x, lane = t & 31, wy = t >> 5;

    if ((int)blockIdx.x >= ntiles) {
        // ---------------- staging GEMM: z = (x*rout) @ W1 ----------------
        const int row0 = (blockIdx.x - ntiles) * 64;
#pragma unroll
        for (int i = 0; i < (D * D) / 256; i++) {
            int m = t + 256 * i;
            WsT[m & (D - 1)][m >> 6] = W1[m];      // col = m%64, k = m/64
        }
        for (int idx = t; idx < 64 * (D / 4); idx += 256) {
            int r = idx >> 4, c4 = idx & 15;
            int row = row0 + r;
            float4 v = make_float4(0.f, 0.f, 0.f, 0.f);
            if (row < n) {
                float rt = rsqrtf(1.0f + (float)g_cnt_out[row]);
                v = ((const float4*)x)[row * 16 + c4];
                v.x *= rt; v.y *= rt; v.z *= rt; v.w *= rt;
            }
            *(float4*)&Us[r][c4 * 4] = v;
        }
        __syncthreads();

        // thread: 8 rows (wy*8+r) x cols (lane, lane+32)
        float acc[8][2];
#pragma unroll
        for (int r = 0; r < 8; r++) { acc[r][0] = 0.f; acc[r][1] = 0.f; }
#pragma unroll
        for (int k = 0; k < D; k += 4) {
            float4 w0 = *(const float4*)&WsT[lane][k];
            float4 w1 = *(const float4*)&WsT[lane + 32][k];
#pragma unroll
            for (int r = 0; r < 8; r++) {
                float4 u = *(const float4*)&Us[wy * 8 + r][k];
                acc[r][0] = fmaf(u.x, w0.x, acc[r][0]);
                acc[r][0] = fmaf(u.y, w0.y, acc[r][0]);
                acc[r][0] = fmaf(u.z, w0.z, acc[r][0]);
                acc[r][0] = fmaf(u.w, w0.w, acc[r][0]);
                acc[r][1] = fmaf(u.x, w1.x, acc[r][1]);
                acc[r][1] = fmaf(u.y, w1.y, acc[r][1]);
                acc[r][1] = fmaf(u.z, w1.z, acc[r][1]);
                acc[r][1] = fmaf(u.w, w1.w, acc[r][1]);
            }
        }
#pragma unroll
        for (int r = 0; r < 8; r++) {
            int row = row0 + wy * 8 + r;
            if (row < n)
                g_z[row * 32 + lane] = __floats2half2_rn(acc[r][0], acc[r][1]);
        }
        return;
    }

    // ----------------------------- scan tile -----------------------------
    if (t == 0) sh_tile = (int)atomicAdd(&g_scan_ticket, 1u);
    __syncthreads();
    const int tile = sh_tile;
    const int base = tile * SCAN_TILE;

    int i0 = base + t * 4;
    int4 v = make_int4(0, 0, 0, 0);
    if (i0 + 3 < n) v = *(const int4*)&g_cnt_in[i0];
    else {
        if (i0     < n) v.x = g_cnt_in[i0];
        if (i0 + 1 < n) v.y = g_cnt_in[i0 + 1];
        if (i0 + 2 < n) v.z = g_cnt_in[i0 + 2];
        if (i0 + 3 < n) v.w = g_cnt_in[i0 + 3];
    }
    int tsum = v.x + v.y + v.z + v.w;

    int sc = tsum;
#pragma unroll
    for (int o = 1; o < 32; o <<= 1) {
        int y = __shfl_up_sync(FULL, sc, o);
        if (lane >= o) sc += y;
    }
    if (lane == 31) warp_agg[wy] = sc;
    __syncthreads();
    if (t < 8) {
        int w = warp_agg[t];
#pragma unroll
        for (int o = 1; o < 8; o <<= 1) {
            int y = __shfl_up_sync(0xffu, w, o);
            if (t >= o) w += y;
        }
        warp_agg[t] = w;
    }
    __syncthreads();
    const int blk_total = warp_agg[7];
    const int texcl = ((wy > 0) ? warp_agg[wy - 1] : 0) + sc - tsum;

    if (t == 0) {
        if (tile == 0) {
            atomicExch(&g_desc[0], (2ULL << 32) | (unsigned)blk_total);
            sh_prefix = 0;
        } else {
            atomicExch(&g_desc[tile], (1ULL << 32) | (unsigned)blk_total);
            int pfx = 0;
            for (int k = tile - 1; k >= 0; k--) {
                unsigned long long d;
                do {
                    d = atomicAdd(&g_desc[k], 0ULL);
                    if ((d >> 32) == 0ULL) __nanosleep(40);
                } while ((d >> 32) == 0ULL);
                pfx += (int)(unsigned)d;
                if ((d >> 32) == 2ULL) break;
            }
            atomicExch(&g_desc[tile], (2ULL << 32) | (unsigned)(pfx + blk_total));
            sh_prefix = pfx;
        }
    }
    __syncthreads();

    int e0 = sh_prefix + texcl;
    int e1 = e0 + v.x, e2 = e1 + v.y, e3 = e2 + v.z;
    if (i0     < n) { g_row_ptr[i0]     = e0; g_cursor[i0]     = e0; }
    if (i0 + 1 < n) { g_row_ptr[i0 + 1] = e1; g_cursor[i0 + 1] = e1; }
    if (i0 + 2 < n) { g_row_ptr[i0 + 2] = e2; g_cursor[i0 + 2] = e2; }
    if (i0 + 3 < n) { g_row_ptr[i0 + 3] = e3; g_cursor[i0 + 3] = e3; }
    if (i0     == n - 1) g_row_ptr[n] = e1;
    if (i0 + 1 == n - 1) g_row_ptr[n] = e2;
    if (i0 + 2 == n - 1) g_row_ptr[n] = e3;
    if (i0 + 3 == n - 1) g_row_ptr[n] = e3 + v.w;
}

// ------------------------------- CSR fill ----------------------------------

__global__ void k_fill(const int* __restrict__ src, const int* __restrict__ dst,
                       int e, int n) {
    int t = blockIdx.x * blockDim.x + threadIdx.x;
    if (t >= e) return;
    int s = clampi(src[t], n);
    int d = clampi(dst[t], n);
    int pos = atomicAdd(&g_cursor[d], 1);
    g_csr[pos] = s;
}

// -------------------- pure gather + q (warp per row) ------------------------
// Lane owns feature pair (lane, lane+32) = one __half2 (4 B) per row.
// Coalesced csr read per 32 edges, shuffles distribute, 4 loads in flight.

__global__ __launch_bounds__(256)
void k_agg_q(const float* __restrict__ b1, const float* __restrict__ W2,
             const float* __restrict__ Wr, int n) {
    __shared__ float w2s[D];
    const int t = threadIdx.x, lane = t & 31, wy = t >> 5;
    if (t < D) {
        float s = 0.f;
#pragma unroll
        for (int j = 0; j < D; j++) s += W2[t * D + j] * Wr[j];
        w2s[t] = s;
    }
    __syncthreads();

    int row = blockIdx.x * 8 + wy;
    if (row >= n) return;

    const float2 wf  = make_float2(w2s[lane], w2s[lane + 32]);
    const float2 b1f = make_float2(__ldg(&b1[lane]), __ldg(&b1[lane + 32]));
    const __half2* z2 = (const __half2*)g_z;    // row stride 32 half2

    float2 acc = __half22float2(z2[row * 32 + lane]);   // self term
    float2 acc2 = make_float2(0.f, 0.f);

    int start = g_row_ptr[row], end = g_row_ptr[row + 1];
    for (int base = start; base < end; base += 32) {
        int cnt = min(32, end - base);
        int idx = g_csr[base + min(lane, cnt - 1)];     // coalesced
        int k = 0;
        for (; k + 4 <= cnt; k += 4) {
            int s0 = __shfl_sync(FULL, idx, k);
            int s1 = __shfl_sync(FULL, idx, k + 1);
            int s2 = __shfl_sync(FULL, idx, k + 2);
            int s3 = __shfl_sync(FULL, idx, k + 3);
            __half2 q0 = z2[s0 * 32 + lane];
            __half2 q1 = z2[s1 * 32 + lane];
            __half2 q2 = z2[s2 * 32 + lane];
            __half2 q3 = z2[s3 * 32 + lane];
            float2 f0 = __half22float2(q0), f1 = __half22float2(q1);
            float2 f2 = __half22float2(q2), f3 = __half22float2(q3);
            acc.x += f0.x; acc.y += f0.y;  acc2.x += f1.x; acc2.y += f1.y;
            acc.x += f2.x; acc.y += f2.y;  acc2.x += f3.x; acc2.y += f3.y;
        }
        for (; k < cnt; k++) {
            int s0 = __shfl_sync(FULL, idx, k);
            float2 f0 = __half22float2(z2[s0 * 32 + lane]);
            acc.x += f0.x; acc.y += f0.y;
        }
    }
    acc.x += acc2.x; acc.y += acc2.y;

    float rin = rsqrtf(1.0f + (float)g_cnt_in[row]);
    float y0 = fmaxf(fmaf(acc.x, rin, b1f.x), 0.f);
    float y1 = fmaxf(fmaf(acc.y, rin, b1f.y), 0.f);
    float p = y0 * wf.x + y1 * wf.y;
#pragma unroll
    for (int o = 16; o; o >>= 1) p += __shfl_xor_sync(FULL, p, o);
    if (lane == 0)
        g_q[row] = p * rsqrtf(1.0f + (float)g_cnt_out[row]);
}

// -------------------- layer-2 gather + finalize (fused) ---------------------

__global__ void k_out(const float* __restrict__ b2, const float* __restrict__ Wr,
                      const float* __restrict__ br, float* __restrict__ out, int n) {
    __shared__ float c_sh;
    if (threadIdx.x == 0) {
        float c = 0.f;
        for (int j = 0; j < D; j++) c += b2[j] * Wr[j];
        c_sh = c + br[0];
    }
    __syncthreads();
    int node = (blockIdx.x * blockDim.x + threadIdx.x) >> 4;
    int lane = threadIdx.x & 15;
    if (node >= n) return;
    int start = g_row_ptr[node], end = g_row_ptr[node + 1];
    float s = 0.f;
    for (int j = start + lane; j < end; j += 16)
        s += g_q[g_csr[j]];
#pragma unroll
    for (int o = 8; o; o >>= 1) s += __shfl_xor_sync(FULL, s, o, 16);
    if (lane == 0) {
        float rin = rsqrtf(1.0f + (float)g_cnt_in[node]);
        out[node] = fmaf(s + g_q[node], rin, c_sh);
    }
}

// -------------------------- trailing state reset ----------------------------

__global__ void k_reset(int n, int ntiles) {
    int i = blockIdx.x * 256 + threadIdx.x;
    if (i < n) { g_cnt_out[i] = 0; g_cnt_in[i] = 0; }
    if (i < ntiles) g_desc[i] = 0ULL;
    if (i == 0) g_scan_ticket = 0u;
}

// ------------------------------- launch -------------------------------------

extern "C" void kernel_launch(void* const* d_in, const int* in_sizes, int n_in,
                              void* d_out, int out_size) {
    const float* x   = (const float*)d_in[0];
    const int*   src = (const int*)d_in[1];
    const int*   dst = (const int*)d_in[2];
    const float* W1  = (const float*)d_in[3];
    const float* b1  = (const float*)d_in[4];
    const float* W2  = (const float*)d_in[5];
    const float* b2  = (const float*)d_in[6];
    const float* Wr  = (const float*)d_in[7];
    const float* br  = (const float*)d_in[8];
    float*       out = (float*)d_out;

    const int n = in_sizes[0] / D;
    const int e = in_sizes[1];
    const int ntiles = (n + SCAN_TILE - 1) / SCAN_TILE;
    const int gemm_blocks = (n + 63) / 64;

    k_deg<<<(e + 255) / 256, 256>>>(src, dst, e, n);                 // 0
    k_scan_stage<<<ntiles + gemm_blocks, 256>>>(x, W1, n, ntiles);   // 1
    k_fill<<<(e + 255) / 256, 256>>>(src, dst, e, n);                // 2
    k_agg_q<<<(n + 7) / 8, 256>>>(b1, W2, Wr, n);                    // 3 (ncu)
    k_out<<<((n * 16) + 255) / 256, 256>>>(b2, Wr, br, out, n);      // 4
    k_reset<<<(n + 255) / 256, 256>>>(n, ntiles);                    // 5
}

// round 16
// speedup vs baseline: 1.9125x; 1.9125x over previous
#include <cuda_runtime.h>
#include <cuda_fp16.h>
#include <stdint.h>
#include <stdlib.h>

// ---------------------------------------------------------------------------
// GCN 2-layer forward, N=100k, E=1.6M, d=64.
// z = (x*rout)@W1 staged fp16 (GEMM commuted out of the gather);
// layer 1 = pure gather q = rout*(relu(rin*(z_self+Sum z[src])+b1) . w2r);
// layer 2 = scalar gather of q.
// Gather kernel uses R12's measured-best loop: half-warp per edge stream,
// DIRECT csr broadcast loads (no per-edge shuffles -- SHFL shares the MIO/L1
// port and saturated it in R15), 4-edge unroll, no smem tiles, no syncs.
// Pipeline: deg(0) scan+stageGEMM(1) fill(2) agg_q(3=ncu slot) out(4) reset(5)
// ---------------------------------------------------------------------------

#define MAXN 100352
#define MAXE 1605632
#define D 64
#define WPAD 68                      // 272B row stride: 16B-aligned, no conflicts
#define FULL 0xffffffffu
#define SCAN_TILE 1024
#define MAX_TILES ((MAXN + SCAN_TILE - 1) / SCAN_TILE)

__device__ int   g_cnt_out[MAXN];
__device__ int   g_cnt_in[MAXN];
__device__ int   g_row_ptr[MAXN + 1];
__device__ int   g_cursor[MAXN];
__device__ int   g_csr[MAXE];              // src only (4 B/edge)
__device__ __half2 g_z[MAXN * D / 2];      // staged z, fp16; half2 L = (featL, featL+32)
__device__ float g_q[MAXN];
__device__ unsigned long long g_desc[MAX_TILES];  // lookback: status<<32 | value
__device__ unsigned g_scan_ticket;

__attribute__((constructor))
static void _eager_modules() { setenv("CUDA_MODULE_LOADING", "EAGER", 1); }

__device__ __forceinline__ int clampi(int v, int n) { return min(max(v, 0), n - 1); }

// ------------------------------- degrees -----------------------------------

__global__ void k_deg(const int* __restrict__ src, const int* __restrict__ dst,
                      int e, int n) {
    int t = blockIdx.x * blockDim.x + threadIdx.x;
    if (t >= e) return;
    atomicAdd(&g_cnt_out[clampi(src[t], n)], 1);
    atomicAdd(&g_cnt_in[clampi(dst[t], n)], 1);
}

// ------- single-pass scan (decoupled lookback) + staging GEMM blocks --------

__global__ __launch_bounds__(256)
void k_scan_stage(const float* __restrict__ x, const float* __restrict__ W1,
                  int n, int ntiles) {
    __shared__ float WsT[D][WPAD];       // 17 KB (gemm blocks)
    __shared__ float Us[64][D];          // 16 KB (gemm blocks)
    __shared__ int   sh_tile, sh_prefix;
    __shared__ int   warp_agg[8];

    const int t = threadIdx.x, lane = t & 31, wy = t >> 5;

    if ((int)blockIdx.x >= ntiles) {
        // ---------------- staging GEMM: z = (x*rout) @ W1 ----------------
        const int row0 = (blockIdx.x - ntiles) * 64;
#pragma unroll
        for (int i = 0; i < (D * D) / 256; i++) {
            int m = t + 256 * i;
            WsT[m & (D - 1)][m >> 6] = W1[m];      // col = m%64, k = m/64
        }
        for (int idx = t; idx < 64 * (D / 4); idx += 256) {
            int r = idx >> 4, c4 = idx & 15;
            int row = row0 + r;
            float4 v = make_float4(0.f, 0.f, 0.f, 0.f);
            if (row < n) {
                float rt = rsqrtf(1.0f + (float)g_cnt_out[row]);
                v = ((const float4*)x)[row * 16 + c4];
                v.x *= rt; v.y *= rt; v.z *= rt; v.w *= rt;
            }
            *(float4*)&Us[r][c4 * 4] = v;
        }
        __syncthreads();

        // thread: 8 rows (wy*8+r) x cols (lane, lane+32)
        float acc[8][2];
#pragma unroll
        for (int r = 0; r < 8; r++) { acc[r][0] = 0.f; acc[r][1] = 0.f; }
#pragma unroll
        for (int k = 0; k < D; k += 4) {
            float4 w0 = *(const float4*)&WsT[lane][k];
            float4 w1 = *(const float4*)&WsT[lane + 32][k];
#pragma unroll
            for (int r = 0; r < 8; r++) {
                float4 u = *(const float4*)&Us[wy * 8 + r][k];
                acc[r][0] = fmaf(u.x, w0.x, acc[r][0]);
                acc[r][0] = fmaf(u.y, w0.y, acc[r][0]);
                acc[r][0] = fmaf(u.z, w0.z, acc[r][0]);
                acc[r][0] = fmaf(u.w, w0.w, acc[r][0]);
                acc[r][1] = fmaf(u.x, w1.x, acc[r][1]);
                acc[r][1] = fmaf(u.y, w1.y, acc[r][1]);
                acc[r][1] = fmaf(u.z, w1.z, acc[r][1]);
                acc[r][1] = fmaf(u.w, w1.w, acc[r][1]);
            }
        }
#pragma unroll
        for (int r = 0; r < 8; r++) {
            int row = row0 + wy * 8 + r;
            if (row < n)
                g_z[row * 32 + lane] = __floats2half2_rn(acc[r][0], acc[r][1]);
        }
        return;
    }

    // ----------------------------- scan tile -----------------------------
    if (t == 0) sh_tile = (int)atomicAdd(&g_scan_ticket, 1u);
    __syncthreads();
    const int tile = sh_tile;
    const int base = tile * SCAN_TILE;

    int i0 = base + t * 4;
    int4 v = make_int4(0, 0, 0, 0);
    if (i0 + 3 < n) v = *(const int4*)&g_cnt_in[i0];
    else {
        if (i0     < n) v.x = g_cnt_in[i0];
        if (i0 + 1 < n) v.y = g_cnt_in[i0 + 1];
        if (i0 + 2 < n) v.z = g_cnt_in[i0 + 2];
        if (i0 + 3 < n) v.w = g_cnt_in[i0 + 3];
    }
    int tsum = v.x + v.y + v.z + v.w;

    int sc = tsum;
#pragma unroll
    for (int o = 1; o < 32; o <<= 1) {
        int y = __shfl_up_sync(FULL, sc, o);
        if (lane >= o) sc += y;
    }
    if (lane == 31) warp_agg[wy] = sc;
    __syncthreads();
    if (t < 8) {
        int w = warp_agg[t];
#pragma unroll
        for (int o = 1; o < 8; o <<= 1) {
            int y = __shfl_up_sync(0xffu, w, o);
            if (t >= o) w += y;
        }
        warp_agg[t] = w;
    }
    __syncthreads();
    const int blk_total = warp_agg[7];
    const int texcl = ((wy > 0) ? warp_agg[wy - 1] : 0) + sc - tsum;

    if (t == 0) {
        if (tile == 0) {
            atomicExch(&g_desc[0], (2ULL << 32) | (unsigned)blk_total);
            sh_prefix = 0;
        } else {
            atomicExch(&g_desc[tile], (1ULL << 32) | (unsigned)blk_total);
            int pfx = 0;
            for (int k = tile - 1; k >= 0; k--) {
                unsigned long long d;
                do {
                    d = atomicAdd(&g_desc[k], 0ULL);
                    if ((d >> 32) == 0ULL) __nanosleep(40);
                } while ((d >> 32) == 0ULL);
                pfx += (int)(unsigned)d;
                if ((d >> 32) == 2ULL) break;
            }
            atomicExch(&g_desc[tile], (2ULL << 32) | (unsigned)(pfx + blk_total));
            sh_prefix = pfx;
        }
    }
    __syncthreads();

    int e0 = sh_prefix + texcl;
    int e1 = e0 + v.x, e2 = e1 + v.y, e3 = e2 + v.z;
    if (i0     < n) { g_row_ptr[i0]     = e0; g_cursor[i0]     = e0; }
    if (i0 + 1 < n) { g_row_ptr[i0 + 1] = e1; g_cursor[i0 + 1] = e1; }
    if (i0 + 2 < n) { g_row_ptr[i0 + 2] = e2; g_cursor[i0 + 2] = e2; }
    if (i0 + 3 < n) { g_row_ptr[i0 + 3] = e3; g_cursor[i0 + 3] = e3; }
    if (i0     == n - 1) g_row_ptr[n] = e1;
    if (i0 + 1 == n - 1) g_row_ptr[n] = e2;
    if (i0 + 2 == n - 1) g_row_ptr[n] = e3;
    if (i0 + 3 == n - 1) g_row_ptr[n] = e3 + v.w;
}

// ------------------------------- CSR fill ----------------------------------

__global__ void k_fill(const int* __restrict__ src, const int* __restrict__ dst,
                       int e, int n) {
    int t = blockIdx.x * blockDim.x + threadIdx.x;
    if (t >= e) return;
    int s = clampi(src[t], n);
    int d = clampi(dst[t], n);
    int pos = atomicAdd(&g_cursor[d], 1);
    g_csr[pos] = s;
}

// -------------------- gather + q (R12-style loop, no GEMM) ------------------
// Block = 64 rows, 8 warps x 8 rows. Half-warp per edge stream, lane cc owns
// 8 bytes (uint2 = flat halves 4cc..4cc+3, permuted features). Direct csr
// broadcast loads; shuffles only in the per-row combine/reduce (~8 per row).

__device__ __forceinline__ void acc_z(float4& a, uint2 hv) {
    float2 f0 = __half22float2(*(__half2*)&hv.x);
    float2 f1 = __half22float2(*(__half2*)&hv.y);
    a.x += f0.x; a.y += f0.y; a.z += f1.x; a.w += f1.y;
}

__global__ __launch_bounds__(256)
void k_agg_q(const float* __restrict__ b1, const float* __restrict__ W2,
             const float* __restrict__ Wr, int n) {
    __shared__ float w2p[D], b1p[D];     // permuted: slot i <-> feature perm(i)
    const int t = threadIdx.x, lane = t & 31, wy = t >> 5;
    if (t < D) {
        int f = (t >> 1) + (t & 1) * 32;           // perm: even->i/2, odd->i/2+32
        float s = 0.f;
#pragma unroll
        for (int j = 0; j < D; j++) s += W2[f * D + j] * Wr[j];
        w2p[t] = s;
        b1p[t] = b1[f];
    }
    __syncthreads();

    const int half = lane >> 4, cc = lane & 15;
    const uint2* z2 = (const uint2*)g_z;           // 16 uint2 per row (128 B)
    const float4 wf  = *(const float4*)&w2p[cc * 4];
    const float4 bf  = *(const float4*)&b1p[cc * 4];

    for (int r = 0; r < 8; r++) {
        int row = blockIdx.x * 64 + wy * 8 + r;
        if (row >= n) continue;                     // warp-uniform
        int start = g_row_ptr[row], end = g_row_ptr[row + 1];

        float4 a = make_float4(0.f, 0.f, 0.f, 0.f);
        float4 b = make_float4(0.f, 0.f, 0.f, 0.f);

        if (half == 0)                              // self term
            acc_z(a, z2[row * 16 + cc]);

        int j = start + half;                        // halves interleave edges
        for (; j + 6 < end; j += 8) {                // 4 edges/half in flight
            int s0 = g_csr[j], s1 = g_csr[j + 2], s2 = g_csr[j + 4], s3 = g_csr[j + 6];
            uint2 q0 = z2[s0 * 16 + cc];
            uint2 q1 = z2[s1 * 16 + cc];
            uint2 q2 = z2[s2 * 16 + cc];
            uint2 q3 = z2[s3 * 16 + cc];
            acc_z(a, q0); acc_z(b, q1); acc_z(a, q2); acc_z(b, q3);
        }
        for (; j < end; j += 2)
            acc_z(a, z2[g_csr[j] * 16 + cc]);

        a.x += b.x; a.y += b.y; a.z += b.z; a.w += b.w;
        a.x += __shfl_xor_sync(FULL, a.x, 16);       // combine halves
        a.y += __shfl_xor_sync(FULL, a.y, 16);
        a.z += __shfl_xor_sync(FULL, a.z, 16);
        a.w += __shfl_xor_sync(FULL, a.w, 16);

        float rin = rsqrtf(1.0f + (float)g_cnt_in[row]);
        float y0 = fmaxf(fmaf(a.x, rin, bf.x), 0.f);
        float y1 = fmaxf(fmaf(a.y, rin, bf.y), 0.f);
        float y2 = fmaxf(fmaf(a.z, rin, bf.z), 0.f);
        float y3 = fmaxf(fmaf(a.w, rin, bf.w), 0.f);
        float p = y0 * wf.x + y1 * wf.y + y2 * wf.z + y3 * wf.w;
#pragma unroll
        for (int o = 8; o; o >>= 1) p += __shfl_xor_sync(FULL, p, o); // 16-group
        if (lane == 0)
            g_q[row] = p * rsqrtf(1.0f + (float)g_cnt_out[row]);
    }
}

// -------------------- layer-2 gather + finalize (fused) ---------------------

__global__ void k_out(const float* __restrict__ b2, const float* __restrict__ Wr,
                      const float* __restrict__ br, float* __restrict__ out, int n) {
    __shared__ float c_sh;
    if (threadIdx.x == 0) {
        float c = 0.f;
        for (int j = 0; j < D; j++) c += b2[j] * Wr[j];
        c_sh = c + br[0];
    }
    __syncthreads();
    int node = (blockIdx.x * blockDim.x + threadIdx.x) >> 4;
    int lane = threadIdx.x & 15;
    if (node >= n) return;
    int start = g_row_ptr[node], end = g_row_ptr[node + 1];
    float s = 0.f;
    for (int j = start + lane; j < end; j += 16)
        s += g_q[g_csr[j]];
#pragma unroll
    for (int o = 8; o; o >>= 1) s += __shfl_xor_sync(FULL, s, o, 16);
    if (lane == 0) {
        float rin = rsqrtf(1.0f + (float)g_cnt_in[node]);
        out[node] = fmaf(s + g_q[node], rin, c_sh);
    }
}

// -------------------------- trailing state reset ----------------------------

__global__ void k_reset(int n, int ntiles) {
    int i = blockIdx.x * 256 + threadIdx.x;
    if (i < n) { g_cnt_out[i] = 0; g_cnt_in[i] = 0; }
    if (i < ntiles) g_desc[i] = 0ULL;
    if (i == 0) g_scan_ticket = 0u;
}

// ------------------------------- launch -------------------------------------

extern "C" void kernel_launch(void* const* d_in, const int* in_sizes, int n_in,
                              void* d_out, int out_size) {
    const float* x   = (const float*)d_in[0];
    const int*   src = (const int*)d_in[1];
    const int*   dst = (const int*)d_in[2];
    const float* W1  = (const float*)d_in[3];
    const float* b1  = (const float*)d_in[4];
    const float* W2  = (const float*)d_in[5];
    const float* b2  = (const float*)d_in[6];
    const float* Wr  = (const float*)d_in[7];
    const float* br  = (const float*)d_in[8];
    float*       out = (float*)d_out;

    const int n = in_sizes[0] / D;
    const int e = in_sizes[1];
    const int ntiles = (n + SCAN_TILE - 1) / SCAN_TILE;
    const int gemm_blocks = (n + 63) / 64;

    k_deg<<<(e + 255) / 256, 256>>>(src, dst, e, n);                 // 0
    k_scan_stage<<<ntiles + gemm_blocks, 256>>>(x, W1, n, ntiles);   // 1
    k_fill<<<(e + 255) / 256, 256>>>(src, dst, e, n);                // 2
    k_agg_q<<<(n + 63) / 64, 256>>>(b1, W2, Wr, n);                  // 3 (ncu)
    k_out<<<((n * 16) + 255) / 256, 256>>>(b2, Wr, br, out, n);      // 4
    k_reset<<<(n + 255) / 256, 256>>>(n, ntiles);                    // 5
}

// round 17
// speedup vs baseline: 2.1305x; 1.1140x over previous
#include <cuda_runtime.h>
#include <cuda_fp16.h>
#include <stdint.h>
#include <stdlib.h>

// ---------------------------------------------------------------------------
// GCN 2-layer forward, N=100k, E=1.6M, d=64.  3-launch pipeline:
//  0 k_prep  : deg (atomics) | barrier | {scan tiles + staging GEMM tiles via
//              combined ticket} | barrier | CSR fill.  Also precomputes
//              w2p/b1p/c.  z=(x*rout)@W1 staged fp16.
//  1 k_agg_q : pure gather (R16 loop, unchanged): half-warp per edge stream,
//              direct csr broadcast loads, 4-edge unroll; epilogue stores q,
//              r2=rin and zeroes cnt arrays (self-resetting state).
//  2 k_out   : scalar gather of q + finalize; resets desc/ticket.
// ---------------------------------------------------------------------------

#define MAXN 100352
#define MAXE 1605632
#define D 64
#define WPAD 68
#define FULL 0xffffffffu
#define SCAN_TILE 1024
#define MAX_TILES ((MAXN + SCAN_TILE - 1) / SCAN_TILE)

__device__ int   g_cnt_out[MAXN];
__device__ int   g_cnt_in[MAXN];
__device__ int   g_row_ptr[MAXN + 1];
__device__ int   g_cursor[MAXN];
__device__ int   g_csr[MAXE];
__device__ __half2 g_z[MAXN * D / 2];      // staged z fp16; half2 L=(featL,featL+32)
__device__ float g_q[MAXN];
__device__ float g_r2[MAXN];               // rin per node (staged for k_out)
__device__ float g_w2p[D], g_b1p[D];       // permuted W2@Wr, b1
__device__ float g_c;
__device__ unsigned long long g_desc[MAX_TILES];
__device__ unsigned g_ticket;
__device__ unsigned g_bar_count;
__device__ unsigned g_bar_gen;

__attribute__((constructor))
static void _eager_modules() { setenv("CUDA_MODULE_LOADING", "EAGER", 1); }

__device__ __forceinline__ int clampi(int v, int n) { return min(max(v, 0), n - 1); }

__device__ __forceinline__ void grid_barrier(int nblocks) {
    __syncthreads();
    if (threadIdx.x == 0) {
        __threadfence();
        unsigned gen = *(volatile unsigned*)&g_bar_gen;
        unsigned old = atomicAdd(&g_bar_count, 1u);
        if (old == (unsigned)nblocks - 1u) {
            g_bar_count = 0u;
            __threadfence();
            atomicAdd(&g_bar_gen, 1u);
        } else {
            while (*(volatile unsigned*)&g_bar_gen == gen) __nanosleep(64);
        }
        __threadfence();
    }
    __syncthreads();
}

// ------------------------------ prep kernel ---------------------------------

__global__ __launch_bounds__(256)
void k_prep(const float* __restrict__ x,
            const int* __restrict__ src, const int* __restrict__ dst,
            const float* __restrict__ W1, const float* __restrict__ b1,
            const float* __restrict__ W2, const float* __restrict__ b2,
            const float* __restrict__ Wr, const float* __restrict__ br,
            int n, int e, int ntiles_scan, int ntickets) {
    __shared__ float WsT[D][WPAD];
    __shared__ float Us[64][D];
    __shared__ int   sh_tile, sh_prefix;
    __shared__ int   warp_agg[8];

    const int nb = gridDim.x;
    const int t = threadIdx.x, lane = t & 31, wy = t >> 5;
    const int gtid = blockIdx.x * 256 + t;
    const int nthr = nb * 256;

    // ---- phase A: degrees (+ block 0 precomputes w2p/b1p/c) ----
    if (blockIdx.x == 0) {
        if (t < D) {
            int f = (t >> 1) + (t & 1) * 32;       // permuted feature slot
            float s = 0.f;
#pragma unroll
            for (int j = 0; j < D; j++) s += W2[f * D + j] * Wr[j];
            g_w2p[t] = s;
            g_b1p[t] = b1[f];
        }
        if (t == 0) {
            float c = 0.f;
            for (int j = 0; j < D; j++) c += b2[j] * Wr[j];
            g_c = c + br[0];
        }
    }
    for (int i = gtid; i < e; i += nthr) {
        atomicAdd(&g_cnt_out[clampi(src[i], n)], 1);
        atomicAdd(&g_cnt_in[clampi(dst[i], n)], 1);
    }
    grid_barrier(nb);

    // load W1 transposed once per block (used by gemm tiles)
#pragma unroll
    for (int i = 0; i < (D * D) / 256; i++) {
        int m = t + 256 * i;
        WsT[m & (D - 1)][m >> 6] = W1[m];
    }

    // ---- phase B: combined ticket loop: scan tiles then gemm tiles ----
    for (;;) {
        if (t == 0) sh_tile = (int)atomicAdd(&g_ticket, 1u);
        __syncthreads();
        int tk = sh_tile;
        if (tk >= ntickets) break;

        if (tk < ntiles_scan) {
            // ------------- scan tile (decoupled lookback) -------------
            const int tile = tk;
            const int base = tile * SCAN_TILE;
            int i0 = base + t * 4;
            int4 v = make_int4(0, 0, 0, 0);
            if (i0 + 3 < n) v = *(const int4*)&g_cnt_in[i0];
            else {
                if (i0     < n) v.x = g_cnt_in[i0];
                if (i0 + 1 < n) v.y = g_cnt_in[i0 + 1];
                if (i0 + 2 < n) v.z = g_cnt_in[i0 + 2];
                if (i0 + 3 < n) v.w = g_cnt_in[i0 + 3];
            }
            int tsum = v.x + v.y + v.z + v.w;
            int sc = tsum;
#pragma unroll
            for (int o = 1; o < 32; o <<= 1) {
                int y = __shfl_up_sync(FULL, sc, o);
                if (lane >= o) sc += y;
            }
            if (lane == 31) warp_agg[wy] = sc;
            __syncthreads();
            if (t < 8) {
                int w = warp_agg[t];
#pragma unroll
                for (int o = 1; o < 8; o <<= 1) {
                    int y = __shfl_up_sync(0xffu, w, o);
                    if (t >= o) w += y;
                }
                warp_agg[t] = w;
            }
            __syncthreads();
            const int blk_total = warp_agg[7];
            const int texcl = ((wy > 0) ? warp_agg[wy - 1] : 0) + sc - tsum;

            if (t == 0) {
                if (tile == 0) {
                    atomicExch(&g_desc[0], (2ULL << 32) | (unsigned)blk_total);
                    sh_prefix = 0;
                } else {
                    atomicExch(&g_desc[tile], (1ULL << 32) | (unsigned)blk_total);
                    int pfx = 0;
                    for (int k = tile - 1; k >= 0; k--) {
                        unsigned long long d;
                        do {
                            d = atomicAdd(&g_desc[k], 0ULL);
                            if ((d >> 32) == 0ULL) __nanosleep(40);
                        } while ((d >> 32) == 0ULL);
                        pfx += (int)(unsigned)d;
                        if ((d >> 32) == 2ULL) break;
                    }
                    atomicExch(&g_desc[tile], (2ULL << 32) | (unsigned)(pfx + blk_total));
                    sh_prefix = pfx;
                }
            }
            __syncthreads();

            int e0 = sh_prefix + texcl;
            int e1 = e0 + v.x, e2 = e1 + v.y, e3 = e2 + v.z;
            if (i0     < n) { g_row_ptr[i0]     = e0; g_cursor[i0]     = e0; }
            if (i0 + 1 < n) { g_row_ptr[i0 + 1] = e1; g_cursor[i0 + 1] = e1; }
            if (i0 + 2 < n) { g_row_ptr[i0 + 2] = e2; g_cursor[i0 + 2] = e2; }
            if (i0 + 3 < n) { g_row_ptr[i0 + 3] = e3; g_cursor[i0 + 3] = e3; }
            if (i0     == n - 1) g_row_ptr[n] = e1;
            if (i0 + 1 == n - 1) g_row_ptr[n] = e2;
            if (i0 + 2 == n - 1) g_row_ptr[n] = e3;
            if (i0 + 3 == n - 1) g_row_ptr[n] = e3 + v.w;
        } else {
            // ---------------- staging GEMM tile: 64 rows ----------------
            const int row0 = (tk - ntiles_scan) * 64;
            for (int idx = t; idx < 64 * (D / 4); idx += 256) {
                int r = idx >> 4, c4 = idx & 15;
                int row = row0 + r;
                float4 v = make_float4(0.f, 0.f, 0.f, 0.f);
                if (row < n) {
                    float rt = rsqrtf(1.0f + (float)g_cnt_out[row]);
                    v = ((const float4*)x)[row * 16 + c4];
                    v.x *= rt; v.y *= rt; v.z *= rt; v.w *= rt;
                }
                *(float4*)&Us[r][c4 * 4] = v;
            }
            __syncthreads();

            float acc[8][2];
#pragma unroll
            for (int r = 0; r < 8; r++) { acc[r][0] = 0.f; acc[r][1] = 0.f; }
#pragma unroll
            for (int k = 0; k < D; k += 4) {
                float4 w0 = *(const float4*)&WsT[lane][k];
                float4 w1 = *(const float4*)&WsT[lane + 32][k];
#pragma unroll
                for (int r = 0; r < 8; r++) {
                    float4 u = *(const float4*)&Us[wy * 8 + r][k];
                    acc[r][0] = fmaf(u.x, w0.x, acc[r][0]);
                    acc[r][0] = fmaf(u.y, w0.y, acc[r][0]);
                    acc[r][0] = fmaf(u.z, w0.z, acc[r][0]);
                    acc[r][0] = fmaf(u.w, w0.w, acc[r][0]);
                    acc[r][1] = fmaf(u.x, w1.x, acc[r][1]);
                    acc[r][1] = fmaf(u.y, w1.y, acc[r][1]);
                    acc[r][1] = fmaf(u.z, w1.z, acc[r][1]);
                    acc[r][1] = fmaf(u.w, w1.w, acc[r][1]);
                }
            }
#pragma unroll
            for (int r = 0; r < 8; r++) {
                int row = row0 + wy * 8 + r;
                if (row < n)
                    g_z[row * 32 + lane] = __floats2half2_rn(acc[r][0], acc[r][1]);
            }
        }
        __syncthreads();    // protect Us / sh_tile before next ticket
    }
    grid_barrier(nb);

    // ---- phase C: CSR fill ----
    for (int i = gtid; i < e; i += nthr) {
        int s = clampi(src[i], n);
        int d = clampi(dst[i], n);
        int pos = atomicAdd(&g_cursor[d], 1);
        g_csr[pos] = s;
    }
}

// -------------------- gather + q (R16 loop, self-resetting) -----------------

__device__ __forceinline__ void acc_z(float4& a, uint2 hv) {
    float2 f0 = __half22float2(*(__half2*)&hv.x);
    float2 f1 = __half22float2(*(__half2*)&hv.y);
    a.x += f0.x; a.y += f0.y; a.z += f1.x; a.w += f1.y;
}

__global__ __launch_bounds__(256)
void k_agg_q(int n) {
    const int t = threadIdx.x, lane = t & 31, wy = t >> 5;
    const int half = lane >> 4, cc = lane & 15;
    const uint2* z2 = (const uint2*)g_z;
    const float4 wf = *(const float4*)&g_w2p[cc * 4];
    const float4 bf = *(const float4*)&g_b1p[cc * 4];

    for (int r = 0; r < 8; r++) {
        int row = blockIdx.x * 64 + wy * 8 + r;
        if (row >= n) continue;                     // warp-uniform
        int start = g_row_ptr[row], end = g_row_ptr[row + 1];

        float4 a = make_float4(0.f, 0.f, 0.f, 0.f);
        float4 b = make_float4(0.f, 0.f, 0.f, 0.f);

        if (half == 0)                              // self term
            acc_z(a, z2[row * 16 + cc]);

        int j = start + half;                        // halves interleave edges
        for (; j + 6 < end; j += 8) {                // 4 edges/half in flight
            int s0 = g_csr[j], s1 = g_csr[j + 2], s2 = g_csr[j + 4], s3 = g_csr[j + 6];
            uint2 q0 = z2[s0 * 16 + cc];
            uint2 q1 = z2[s1 * 16 + cc];
            uint2 q2 = z2[s2 * 16 + cc];
            uint2 q3 = z2[s3 * 16 + cc];
            acc_z(a, q0); acc_z(b, q1); acc_z(a, q2); acc_z(b, q3);
        }
        for (; j < end; j += 2)
            acc_z(a, z2[g_csr[j] * 16 + cc]);

        a.x += b.x; a.y += b.y; a.z += b.z; a.w += b.w;
        a.x += __shfl_xor_sync(FULL, a.x, 16);
        a.y += __shfl_xor_sync(FULL, a.y, 16);
        a.z += __shfl_xor_sync(FULL, a.z, 16);
        a.w += __shfl_xor_sync(FULL, a.w, 16);

        float rin = rsqrtf(1.0f + (float)g_cnt_in[row]);
        float rot = rsqrtf(1.0f + (float)g_cnt_out[row]);
        float y0 = fmaxf(fmaf(a.x, rin, bf.x), 0.f);
        float y1 = fmaxf(fmaf(a.y, rin, bf.y), 0.f);
        float y2 = fmaxf(fmaf(a.z, rin, bf.z), 0.f);
        float y3 = fmaxf(fmaf(a.w, rin, bf.w), 0.f);
        float p = y0 * wf.x + y1 * wf.y + y2 * wf.z + y3 * wf.w;
#pragma unroll
        for (int o = 8; o; o >>= 1) p += __shfl_xor_sync(FULL, p, o);
        if (lane == 0) g_q[row] = p * rot;
        if (lane == 1) g_r2[row] = rin;
        if (lane == 2) g_cnt_in[row] = 0;           // after all reads of cnt
        if (lane == 3) g_cnt_out[row] = 0;
    }
}

// ------------- layer-2 gather + finalize; resets desc/ticket ----------------

__global__ void k_out(float* __restrict__ out, int n, int ntiles_scan) {
    int gt = blockIdx.x * blockDim.x + threadIdx.x;
    if (gt < ntiles_scan) g_desc[gt] = 0ULL;
    if (gt == ntiles_scan) g_ticket = 0u;
    int node = gt >> 4;
    int lane = threadIdx.x & 15;
    if (node >= n) return;
    int start = g_row_ptr[node], end = g_row_ptr[node + 1];
    float s = 0.f;
    for (int j = start + lane; j < end; j += 16)
        s += g_q[g_csr[j]];
#pragma unroll
    for (int o = 8; o; o >>= 1) s += __shfl_xor_sync(FULL, s, o, 16);
    if (lane == 0)
        out[node] = fmaf(s + g_q[node], g_r2[node], g_c);
}

// ------------------------------- launch -------------------------------------

extern "C" void kernel_launch(void* const* d_in, const int* in_sizes, int n_in,
                              void* d_out, int out_size) {
    const float* x   = (const float*)d_in[0];
    const int*   src = (const int*)d_in[1];
    const int*   dst = (const int*)d_in[2];
    const float* W1  = (const float*)d_in[3];
    const float* b1  = (const float*)d_in[4];
    const float* W2  = (const float*)d_in[5];
    const float* b2  = (const float*)d_in[6];
    const float* Wr  = (const float*)d_in[7];
    const float* br  = (const float*)d_in[8];
    float*       out = (float*)d_out;

    const int n = in_sizes[0] / D;
    const int e = in_sizes[1];
    const int ntiles_scan = (n + SCAN_TILE - 1) / SCAN_TILE;
    const int ntickets = ntiles_scan + (n + 63) / 64;

    int dev = 0, sms = 0, occ = 0;
    cudaGetDevice(&dev);
    cudaDeviceGetAttribute(&sms, cudaDevAttrMultiProcessorCount, dev);
    cudaOccupancyMaxActiveBlocksPerMultiprocessor(&occ, k_prep, 256, 0);
    if (sms < 1) sms = 1;
    if (occ < 1) occ = 1;
    int nb = sms * occ;
    if (nb > 2048) nb = 2048;

    k_prep<<<nb, 256>>>(x, src, dst, W1, b1, W2, b2, Wr, br,
                        n, e, ntiles_scan, ntickets);
    k_agg_q<<<(n + 63) / 64, 256>>>(n);
    k_out<<<((n * 16) + 255) / 256, 256>>>(out, n, ntiles_scan);
}